// round 4
// baseline (speedup 1.0000x reference)
#include <cuda_runtime.h>
#include <cuda_bf16.h>
#include <math.h>
#include <stdint.h>

#define NB_  32
#define NH_  64
#define ND_  512
#define NROPE_ 64
#define NHALF_ 32
#define SMAX_ 4096
#define BS_  64
#define IH_  64
#define ID_  128
#define TOPK_ 512
#define SCALE_ 0.04419417382415922f

typedef unsigned long long ull;

// ---------------- scratch ----------------
__device__ float    g_qr[NB_*NH_*ND_];
__device__ unsigned g_qq[NB_*IH_*32];
__device__ float    g_qs[NB_*IH_];
__device__ float    g_iscore[NB_*SMAX_];
__device__ int      g_sel[NB_*(TOPK_+1)];
__device__ int      g_nsel[NB_];
__device__ float    g_pO[NB_*4*2*16*512];     // partial outputs (8 MB)
__device__ float2   g_pml[NB_*4*2*16];        // (m, l) per split per head

// ---------------- f32x2 helpers ----------------
#define FMA2(d, a, b, c) asm("fma.rn.f32x2 %0, %1, %2, %3;" : "=l"(d) : "l"(a), "l"(b), "l"(c))
__device__ __forceinline__ ull dup2(float x){ ull r; asm("mov.b64 %0, {%1, %1};" : "=l"(r) : "f"(x)); return r; }
__device__ __forceinline__ float2 unpack2(ull v){ float2 r; asm("mov.b64 {%0, %1}, %2;" : "=f"(r.x), "=f"(r.y) : "l"(v)); return r; }

// ---------------- cp.async helpers ----------------
__device__ __forceinline__ void cpa16(void* dst_s, const void* src, int sz) {
    unsigned ds = (unsigned)__cvta_generic_to_shared(dst_s);
    asm volatile("cp.async.cg.shared.global [%0], [%1], 16, %2;" :: "r"(ds), "l"(src), "r"(sz));
}
#define CP_COMMIT() asm volatile("cp.async.commit_group;")
#define CP_WAIT0()  asm volatile("cp.async.wait_group 0;")

// ---------------- kernel 1: fused rope + q_idx quant ----------------
__device__ __forceinline__ int quant1(float x, float scale) {
    float r = rintf(x / scale);
    r = fminf(fmaxf(r, -128.f), 127.f);
    return (int)r;
}

__global__ void prep_kernel(const float* __restrict__ q,
                            const float* __restrict__ cosp,
                            const float* __restrict__ sinp,
                            const float* __restrict__ q_idx) {
    int t = threadIdx.x;
    if (blockIdx.x < 1024) {
        int bh = blockIdx.x * 2 + (t >> 7);
        int b  = bh >> 6;
        int d  = (t & 127) * 4;
        const float* src = q + (size_t)bh * ND_;
        float4 v = *(const float4*)(src + d);
        float4 o;
        if (d < ND_ - NROPE_) {
            o = v;
        } else {
            int i0 = (d - (ND_ - NROPE_)) >> 1;
            float c0 = cosp[b*NHALF_ + i0],   s0 = sinp[b*NHALF_ + i0];
            float c1 = cosp[b*NHALF_ + i0+1], s1 = sinp[b*NHALF_ + i0+1];
            o.x = v.x*c0 - v.y*s0;
            o.y = v.x*s0 + v.y*c0;
            o.z = v.z*c1 - v.w*s1;
            o.w = v.z*s1 + v.w*c1;
        }
        *(float4*)(g_qr + (size_t)bh*ND_ + d) = o;
    } else {
        int row  = (blockIdx.x - 1024) * 8 + (t >> 5);
        int lane = t & 31;
        float4 v = *(const float4*)(q_idx + (size_t)row*ID_ + lane*4);
        float m = fmaxf(fmaxf(fabsf(v.x), fabsf(v.y)), fmaxf(fabsf(v.z), fabsf(v.w)));
        #pragma unroll
        for (int o = 16; o; o >>= 1) m = fmaxf(m, __shfl_xor_sync(0xffffffffu, m, o));
        float scale = fmaxf(m, 1e-12f) * (1.f/127.f);
        if (scale < 1e-6f) scale = 1.f;
        int q0 = quant1(v.x, scale), q1 = quant1(v.y, scale);
        int q2 = quant1(v.z, scale), q3 = quant1(v.w, scale);
        unsigned w = (q0 & 0xFF) | ((q1 & 0xFF) << 8) | ((q2 & 0xFF) << 16) | ((q3 & 0xFF) << 24);
        g_qq[row*32 + lane] = w;
        if (lane == 0) g_qs[row] = scale;
    }
}

// ---------------- kernel 2: indexer scores (2-key ILP) ----------------
__global__ void indexer_kernel(const float* __restrict__ k_idx_cache,
                               const int* __restrict__ btbl,
                               const int* __restrict__ seq_lens) {
    __shared__ unsigned sqq[IH_*33];
    __shared__ float    sqs[IH_];
    int b = blockIdx.y, chunk = blockIdx.x;
    for (int i = threadIdx.x; i < IH_*32; i += 256) {
        int h = i >> 5, w = i & 31;
        sqq[h*33 + w] = g_qq[b*IH_*32 + i];
    }
    if (threadIdx.x < IH_) sqs[threadIdx.x] = g_qs[b*IH_ + threadIdx.x];
    __syncthreads();

    int lane = threadIdx.x & 31, wrp = threadIdx.x >> 5;
    int seqlen = seq_lens[b];
    float negInf = __int_as_float(0xff800000);
    const unsigned* qh0 = sqq + lane*33;
    const unsigned* qh1 = sqq + (lane+32)*33;
    float qs0 = sqs[lane], qs1 = sqs[lane+32];

    for (int i = 0; i < 16; i++) {
        int sA = chunk*256 + i*16 + wrp*2;
        int sB = sA + 1;
        int cA = min(sA, seqlen-1), cB = min(sB, seqlen-1);
        int pgA = btbl[(b << 6) + (cA >> 6)];
        int pgB = btbl[(b << 6) + (cB >> 6)];
        const float* krA = k_idx_cache + ((size_t)pgA*BS_ + (cA & 63)) * ID_;
        const float* krB = k_idx_cache + ((size_t)pgB*BS_ + (cB & 63)) * ID_;
        float4 vA = *(const float4*)(krA + lane*4);
        float4 vB = *(const float4*)(krB + lane*4);
        float mA = fmaxf(fmaxf(fabsf(vA.x), fabsf(vA.y)), fmaxf(fabsf(vA.z), fabsf(vA.w)));
        float mB = fmaxf(fmaxf(fabsf(vB.x), fabsf(vB.y)), fmaxf(fabsf(vB.z), fabsf(vB.w)));
        #pragma unroll
        for (int o = 16; o; o >>= 1) {
            mA = fmaxf(mA, __shfl_xor_sync(0xffffffffu, mA, o));
            mB = fmaxf(mB, __shfl_xor_sync(0xffffffffu, mB, o));
        }
        float scA = fmaxf(mA, 1e-12f) * (1.f/127.f); if (scA < 1e-6f) scA = 1.f;
        float scB = fmaxf(mB, 1e-12f) * (1.f/127.f); if (scB < 1e-6f) scB = 1.f;
        int a0 = quant1(vA.x, scA), a1 = quant1(vA.y, scA), a2 = quant1(vA.z, scA), a3 = quant1(vA.w, scA);
        int b0 = quant1(vB.x, scB), b1 = quant1(vB.y, scB), b2 = quant1(vB.z, scB), b3 = quant1(vB.w, scB);
        unsigned kwA = (a0 & 0xFF) | ((a1 & 0xFF) << 8) | ((a2 & 0xFF) << 16) | ((a3 & 0xFF) << 24);
        unsigned kwB = (b0 & 0xFF) | ((b1 & 0xFF) << 8) | ((b2 & 0xFF) << 16) | ((b3 & 0xFF) << 24);

        int accA0 = 0, accA1 = 0, accB0 = 0, accB1 = 0;
        #pragma unroll
        for (int w = 0; w < 32; w++) {
            unsigned ka = __shfl_sync(0xffffffffu, kwA, w);
            unsigned kb = __shfl_sync(0xffffffffu, kwB, w);
            int qw0 = (int)qh0[w], qw1 = (int)qh1[w];
            accA0 = __dp4a(qw0, (int)ka, accA0);
            accA1 = __dp4a(qw1, (int)ka, accA1);
            accB0 = __dp4a(qw0, (int)kb, accB0);
            accB1 = __dp4a(qw1, (int)kb, accB1);
        }
        float vsA = (float)accA0 * qs0 + (float)accA1 * qs1;
        float vsB = (float)accB0 * qs0 + (float)accB1 * qs1;
        #pragma unroll
        for (int o = 16; o; o >>= 1) {
            vsA += __shfl_xor_sync(0xffffffffu, vsA, o);
            vsB += __shfl_xor_sync(0xffffffffu, vsB, o);
        }
        if (lane == 0) {
            g_iscore[b*SMAX_ + sA] = (sA < seqlen) ? vsA * scA : negInf;
            g_iscore[b*SMAX_ + sB] = (sB < seqlen) ? vsB * scB : negInf;
        }
    }
}

// ---------------- kernel 3: exact top-k, 512 threads ----------------
__device__ __forceinline__ int exscan512(int v, int* sh, int* total) {
    int t = threadIdx.x, lane = t & 31, wid = t >> 5;
    __syncthreads();
    int incl = v;
    #pragma unroll
    for (int o = 1; o < 32; o <<= 1) {
        int n = __shfl_up_sync(0xffffffffu, incl, o);
        if (lane >= o) incl += n;
    }
    if (lane == 31) sh[wid] = incl;
    __syncthreads();
    if (wid == 0) {
        int x = (lane < 16) ? sh[lane] : 0;
        #pragma unroll
        for (int o = 1; o < 16; o <<= 1) {
            int n = __shfl_up_sync(0xffffffffu, x, o);
            if (lane >= o) x += n;
        }
        if (lane < 16) sh[lane] = x;
    }
    __syncthreads();
    int base = wid ? sh[wid-1] : 0;
    *total = sh[15];
    return base + incl - v;
}

__global__ void topk_kernel() {
    int b = blockIdx.x;
    __shared__ unsigned skey[SMAX_];
    __shared__ int hist[256];
    __shared__ int sscan[17];
    __shared__ int sinfo[2];
    __shared__ int stot;
    int t = threadIdx.x;
    int lane = t & 31, wid = t >> 5;

    for (int i = t; i < SMAX_; i += 512) {
        unsigned u = __float_as_uint(g_iscore[b*SMAX_ + i]);
        skey[i] = (u & 0x80000000u) ? ~u : (u | 0x80000000u);
    }
    __syncthreads();

    unsigned prefix = 0, mask = 0;
    int Krem = TOPK_;
    for (int shift = 24; shift >= 0; shift -= 8) {
        if (t < 256) hist[t] = 0;
        __syncthreads();
        for (int i = t; i < SMAX_; i += 512) {
            unsigned u = skey[i];
            if ((u & mask) == prefix) atomicAdd((unsigned*)&hist[(u >> shift) & 255], 1u);
        }
        __syncthreads();
        int c = (t < 256) ? hist[t] : 0;
        int incl = c;
        #pragma unroll
        for (int o = 1; o < 32; o <<= 1) {
            int n = __shfl_up_sync(0xffffffffu, incl, o);
            if (lane >= o) incl += n;
        }
        if (lane == 31 && wid < 8) sscan[wid] = incl;
        __syncthreads();
        if (wid == 0) {
            int x = (lane < 8) ? sscan[lane] : 0;
            #pragma unroll
            for (int o = 1; o < 8; o <<= 1) {
                int n = __shfl_up_sync(0xffffffffu, x, o);
                if (lane >= o) x += n;
            }
            if (lane < 8) sscan[lane] = x;
            if (lane == 7) stot = x;
        }
        __syncthreads();
        if (t < 256) {
            int P = incl + (wid ? sscan[wid-1] : 0);
            int above = stot - P;
            if (above < Krem && Krem <= above + c) {
                sinfo[0] = t;
                sinfo[1] = Krem - above;
            }
        }
        __syncthreads();
        prefix |= ((unsigned)sinfo[0]) << shift;
        mask   |= 0xFFu << shift;
        Krem = sinfo[1];
        __syncthreads();
    }
    unsigned T = prefix;
    int R = Krem;

    int base = t * 8;
    int eqc = 0;
    #pragma unroll
    for (int i = 0; i < 8; i++) eqc += (skey[base+i] == T);
    int tot;
    int eqoff = exscan512(eqc, sscan, &tot);

    int kc = 0;
    unsigned kmask = 0;
    int er = eqoff;
    #pragma unroll
    for (int i = 0; i < 8; i++) {
        unsigned u = skey[base+i];
        bool eq = (u == T);
        bool kp = (u > T) || (eq && er < R);
        er += eq;
        if (base + i == 0) kp = true;
        kmask |= (unsigned)kp << i;
        kc += kp;
    }
    int koff = exscan512(kc, sscan, &tot);
    int p = koff;
    #pragma unroll
    for (int i = 0; i < 8; i++) {
        if ((kmask >> i) & 1) g_sel[b*(TOPK_+1) + p++] = base + i;
    }
    if (t == 0) g_nsel[b] = tot;
}

// ---------------- kernel 4: split-KV attention ----------------
#define SCW 260

struct AttnSmem {
    float q[16][ND_];       // 32768
    float k[2][64][128];    // 65536, XOR-swizzled 16B granules
    float sc[16][SCW];      // 16640
};                          // 114944 B

extern __shared__ char smem_raw[];

__device__ __forceinline__ void prefetch_tile(AttnSmem& S, int buf, int tile, int ch,
                                              int cnt, int selbase,
                                              const float* __restrict__ kv,
                                              const int* __restrict__ btbl,
                                              int bq, int t) {
    int kbase = tile << 6;
    int g = t & 31;
    int dstg = g ^ ((t >> 5) & 7);
    #pragma unroll
    for (int i = 0; i < 8; i++) {
        int r = (t >> 5) + (i << 3);
        int j = kbase + r;
        float* dst = &S.k[buf][r][dstg << 2];
        if (j < cnt) {
            int sp = g_sel[selbase + j];
            int pg = btbl[bq + (sp >> 6)];
            const float* src = kv + ((size_t)pg*BS_ + (sp & 63)) * ND_ + (ch << 7) + (g << 2);
            cpa16(dst, src, 16);
        } else {
            cpa16(dst, kv, 0);
        }
    }
    CP_COMMIT();
}

__global__ void __launch_bounds__(256, 2)
attn_kernel(const float* __restrict__ kv,
            const float* __restrict__ attn_sink,
            const int* __restrict__ btbl,
            float* __restrict__ dummy) {
    AttnSmem& S = *(AttnSmem*)smem_raw;
    int hg = blockIdx.x, b = blockIdx.y, split = blockIdx.z;
    int t = threadIdx.x;
    int nsel = g_nsel[b];
    int hbase = hg * 16;
    int kbeg = split * 256;
    int cnt = (split == 0) ? 256 : (nsel - 256);
    int T = (cnt + 63) >> 6;
    int selbase = b*(TOPK_+1) + kbeg;
    int bq = b << 6;
    int slot = (b*4 + hg)*2 + split;

    // load q
    {
        const float* qr = g_qr + ((size_t)b*NH_ + hbase) * ND_;
        for (int i = t*4; i < 16*ND_; i += 1024)
            *(float4*)&S.q[0][i] = *(const float4*)(qr + i);
    }
    __syncthreads();

    int hq = (t >> 6) << 2;   // 4 heads, warp-uniform
    int kx = t & 31;          // keys kx, kx+32
    int x7 = t & 7;
    float snk[4];
    #pragma unroll
    for (int h = 0; h < 4; h++) snk[h] = attn_sink[hbase + hq + h];

    // ======== phase A: scores ========
    ull accA[4][2];
    prefetch_tile(S, 0, 0, 0, cnt, selbase, kv, btbl, bq, t);
    int T4 = T << 2;
    int buf = 0;
    for (int s = 0; s < T4; s++) {
        CP_WAIT0();
        __syncthreads();
        if (s + 1 < T4) prefetch_tile(S, buf^1, (s+1) >> 2, (s+1) & 3, cnt, selbase, kv, btbl, bq, t);
        else            prefetch_tile(S, buf^1, 0, 0, cnt, selbase, kv, btbl, bq, t); // first C stage
        int tile = s >> 2, ch = s & 3;
        if (ch == 0) {
            #pragma unroll
            for (int h = 0; h < 4; h++) { accA[h][0] = 0ull; accA[h][1] = 0ull; }
        }
        const float* kb0 = &S.k[buf][kx][0];
        const float* kb1 = &S.k[buf][kx+32][0];
        #pragma unroll 8
        for (int g = 0; g < 32; g++) {
            int off = (g ^ x7) << 2;
            ulonglong2 ka = *(const ulonglong2*)(kb0 + off);
            ulonglong2 kc = *(const ulonglong2*)(kb1 + off);
            int d = (ch << 7) + (g << 2);
            #pragma unroll
            for (int h = 0; h < 4; h++) {
                ulonglong2 qa = *(const ulonglong2*)&S.q[hq+h][d];
                FMA2(accA[h][0], qa.x, ka.x, accA[h][0]);
                FMA2(accA[h][0], qa.y, ka.y, accA[h][0]);
                FMA2(accA[h][1], qa.x, kc.x, accA[h][1]);
                FMA2(accA[h][1], qa.y, kc.y, accA[h][1]);
            }
        }
        if (ch == 3) {
            int j0 = (tile << 6) + kx, j1 = j0 + 32;
            #pragma unroll
            for (int h = 0; h < 4; h++) {
                float2 u0 = unpack2(accA[h][0]);
                float2 u1 = unpack2(accA[h][1]);
                float s0 = (u0.x + u0.y) * SCALE_;
                float s1 = (u1.x + u1.y) * SCALE_;
                if (split == 0 && j0 == 0) s0 += snk[h];
                if (j0 < cnt) S.sc[hq+h][j0] = s0;
                if (j1 < cnt) S.sc[hq+h][j1] = s1;
            }
        }
        buf ^= 1;
    }
    __syncthreads();

    // ======== softmax partials (warp per 2 heads) ========
    {
        int wrp = t >> 5, jt = t & 31;
        #pragma unroll
        for (int hh = 0; hh < 2; hh++) {
            int hloc = 2*wrp + hh;
            float m = -3.4e38f;
            for (int j = jt; j < cnt; j += 32) m = fmaxf(m, S.sc[hloc][j]);
            #pragma unroll
            for (int o = 16; o; o >>= 1) m = fmaxf(m, __shfl_xor_sync(0xffffffffu, m, o));
            float sum = 0.f;
            for (int j = jt; j < cnt; j += 32) {
                float e = expf(S.sc[hloc][j] - m);
                S.sc[hloc][j] = e;
                sum += e;
            }
            #pragma unroll
            for (int o = 16; o; o >>= 1) sum += __shfl_xor_sync(0xffffffffu, sum, o);
            if (jt == 0) g_pml[slot*16 + hloc] = make_float2(m, sum);
        }
        if (t < 64) {
            int h = t >> 2, j = cnt + (t & 3);
            if (j < SCW) S.sc[h][j] = 0.f;
        }
    }
    // note: first C-stage data already prefetched

    // ======== phase C: unnormalized output ========
    int pd = t & 63;
    int gC = pd >> 1;
    int o2 = (pd & 1) << 1;
    for (int ch = 0; ch < 4; ch++) {
        ull a0 = 0ull, a1 = 0ull, a2 = 0ull, a3 = 0ull;
        for (int tile = 0; tile < T; tile++) {
            CP_WAIT0();
            __syncthreads();
            int s = ch*T + tile;
            if (s + 1 < 4*T) {
                int ns = s + 1;
                prefetch_tile(S, buf^1, ns % T, ns / T, cnt, selbase, kv, btbl, bq, t);
            }
            int kbase = tile << 6;
            int jmax = cnt - kbase; if (jmax > 64) jmax = 64;
            const float* pw0 = &S.sc[hq+0][kbase];
            const float* pw1 = &S.sc[hq+1][kbase];
            const float* pw2 = &S.sc[hq+2][kbase];
            const float* pw3 = &S.sc[hq+3][kbase];
            const float* kbB = &S.k[buf][0][0];
            if (jmax == 64) {
                #pragma unroll 4
                for (int j = 0; j < 64; j += 4) {
                    float4 w0 = *(const float4*)(pw0 + j);
                    float4 w1 = *(const float4*)(pw1 + j);
                    float4 w2 = *(const float4*)(pw2 + j);
                    float4 w3 = *(const float4*)(pw3 + j);
                    #pragma unroll
                    for (int jj = 0; jj < 4; jj++) {
                        int row = j + jj;
                        ull kp = *(const ull*)(kbB + (row << 7) + ((gC ^ (row & 7)) << 2) + o2);
                        FMA2(a0, dup2((&w0.x)[jj]), kp, a0);
                        FMA2(a1, dup2((&w1.x)[jj]), kp, a1);
                        FMA2(a2, dup2((&w2.x)[jj]), kp, a2);
                        FMA2(a3, dup2((&w3.x)[jj]), kp, a3);
                    }
                }
            } else {
                int j4 = (jmax + 3) & ~3;
                for (int j = 0; j < j4; j += 4) {
                    float4 w0 = *(const float4*)(pw0 + j);
                    float4 w1 = *(const float4*)(pw1 + j);
                    float4 w2 = *(const float4*)(pw2 + j);
                    float4 w3 = *(const float4*)(pw3 + j);
                    #pragma unroll
                    for (int jj = 0; jj < 4; jj++) {
                        int row = j + jj;
                        ull kp = *(const ull*)(kbB + (row << 7) + ((gC ^ (row & 7)) << 2) + o2);
                        FMA2(a0, dup2((&w0.x)[jj]), kp, a0);
                        FMA2(a1, dup2((&w1.x)[jj]), kp, a1);
                        FMA2(a2, dup2((&w2.x)[jj]), kp, a2);
                        FMA2(a3, dup2((&w3.x)[jj]), kp, a3);
                    }
                }
            }
            buf ^= 1;
        }
        // write partials for this chunk
        int dloc = (ch << 7) + (pd << 1);
        float* po = g_pO + ((size_t)slot*16)*ND_;
        float2 u;
        u = unpack2(a0); *(float2*)(po + (size_t)(hq+0)*ND_ + dloc) = u;
        u = unpack2(a1); *(float2*)(po + (size_t)(hq+1)*ND_ + dloc) = u;
        u = unpack2(a2); *(float2*)(po + (size_t)(hq+2)*ND_ + dloc) = u;
        u = unpack2(a3); *(float2*)(po + (size_t)(hq+3)*ND_ + dloc) = u;
    }
}

// ---------------- kernel 5: flash combine ----------------
__global__ void combine_kernel(float* __restrict__ out) {
    int hg = blockIdx.x, b = blockIdx.y;
    int t = threadIdx.x;
    int h = t >> 4;               // 0..15
    int dbase = (t & 15) * 32;
    int slot0 = (b*4 + hg)*2;
    float2 ml0 = g_pml[slot0*16 + h];
    float2 ml1 = g_pml[(slot0+1)*16 + h];
    float M = fmaxf(ml0.x, ml1.x);
    float a0 = expf(ml0.x - M), a1 = expf(ml1.x - M);
    float inv = 1.f / (ml0.y * a0 + ml1.y * a1);
    float c0 = a0 * inv, c1 = a1 * inv;
    const float* p0 = g_pO + ((size_t)slot0*16 + h)*ND_ + dbase;
    const float* p1 = g_pO + ((size_t)(slot0+1)*16 + h)*ND_ + dbase;
    float* po = out + ((size_t)b*NH_ + hg*16 + h)*ND_ + dbase;
    #pragma unroll
    for (int i = 0; i < 8; i++) {
        float4 v0 = *(const float4*)(p0 + i*4);
        float4 v1 = *(const float4*)(p1 + i*4);
        float4 o;
        o.x = v0.x*c0 + v1.x*c1;
        o.y = v0.y*c0 + v1.y*c1;
        o.z = v0.z*c0 + v1.z*c1;
        o.w = v0.w*c0 + v1.w*c1;
        *(float4*)(po + i*4) = o;
    }
}

// ---------------- launch ----------------
extern "C" void kernel_launch(void* const* d_in, const int* in_sizes, int n_in,
                              void* d_out, int out_size) {
    const float* q      = (const float*)d_in[0];
    const float* cosp   = (const float*)d_in[1];
    const float* sinp   = (const float*)d_in[2];
    const float* kv     = (const float*)d_in[3];
    const float* q_idx  = (const float*)d_in[4];
    const float* k_idx  = (const float*)d_in[5];
    const float* sink   = (const float*)d_in[6];
    const int*   btbl   = (const int*)d_in[7];
    const int*   slens  = (const int*)d_in[8];
    float* out = (float*)d_out;

    prep_kernel<<<1280, 256>>>(q, cosp, sinp, q_idx);
    indexer_kernel<<<dim3(16, NB_), 256>>>(k_idx, btbl, slens);
    topk_kernel<<<NB_, 512>>>();

    int smem = (int)sizeof(AttnSmem);
    cudaFuncSetAttribute(attn_kernel, cudaFuncAttributeMaxDynamicSharedMemorySize, smem);
    attn_kernel<<<dim3(4, NB_, 2), 256, smem>>>(kv, sink, btbl, out);
    combine_kernel<<<dim3(4, NB_), 256>>>(out);
}

// round 5
// speedup vs baseline: 2.0464x; 2.0464x over previous
#include <cuda_runtime.h>
#include <cuda_bf16.h>
#include <math.h>
#include <stdint.h>

#define NB_  32
#define NH_  64
#define ND_  512
#define NROPE_ 64
#define NHALF_ 32
#define SMAX_ 4096
#define BS_  64
#define IH_  64
#define ID_  128
#define TOPK_ 512
#define SCALE_ 0.04419417382415922f

typedef unsigned long long ull;

// ---------------- scratch ----------------
__device__ float    g_qr[NB_*NH_*ND_];
__device__ unsigned g_qq[NB_*IH_*32];
__device__ float    g_qs[NB_*IH_];
__device__ float    g_iscore[NB_*SMAX_];
__device__ int      g_sel[NB_*TOPK_];
__device__ int      g_has0[NB_];
__device__ float    g_pO[NB_*4*2*16*512];     // partial outputs
__device__ float2   g_pml[NB_*4*2*16];        // (m, l) per split per head

// ---------------- f32x2 helpers ----------------
#define FMA2(d, a, b, c) asm("fma.rn.f32x2 %0, %1, %2, %3;" : "=l"(d) : "l"(a), "l"(b), "l"(c))
__device__ __forceinline__ ull dup2(float x){ ull r; asm("mov.b64 %0, {%1, %1};" : "=l"(r) : "f"(x)); return r; }
__device__ __forceinline__ float2 unpack2(ull v){ float2 r; asm("mov.b64 {%0, %1}, %2;" : "=f"(r.x), "=f"(r.y) : "l"(v)); return r; }

// ---------------- cp.async helpers ----------------
__device__ __forceinline__ void cpa16(void* dst_s, const void* src) {
    unsigned ds = (unsigned)__cvta_generic_to_shared(dst_s);
    asm volatile("cp.async.cg.shared.global [%0], [%1], 16;" :: "r"(ds), "l"(src));
}
#define CP_COMMIT() asm volatile("cp.async.commit_group;")
#define CP_WAIT0()  asm volatile("cp.async.wait_group 0;")

// ---------------- kernel 1: fused rope + q_idx quant ----------------
__device__ __forceinline__ int quant1(float x, float scale) {
    float r = rintf(x / scale);
    r = fminf(fmaxf(r, -128.f), 127.f);
    return (int)r;
}

__global__ void prep_kernel(const float* __restrict__ q,
                            const float* __restrict__ cosp,
                            const float* __restrict__ sinp,
                            const float* __restrict__ q_idx) {
    int t = threadIdx.x;
    if (blockIdx.x < 1024) {
        int bh = blockIdx.x * 2 + (t >> 7);
        int b  = bh >> 6;
        int d  = (t & 127) * 4;
        const float* src = q + (size_t)bh * ND_;
        float4 v = *(const float4*)(src + d);
        float4 o;
        if (d < ND_ - NROPE_) {
            o = v;
        } else {
            int i0 = (d - (ND_ - NROPE_)) >> 1;
            float c0 = cosp[b*NHALF_ + i0],   s0 = sinp[b*NHALF_ + i0];
            float c1 = cosp[b*NHALF_ + i0+1], s1 = sinp[b*NHALF_ + i0+1];
            o.x = v.x*c0 - v.y*s0;
            o.y = v.x*s0 + v.y*c0;
            o.z = v.z*c1 - v.w*s1;
            o.w = v.z*s1 + v.w*c1;
        }
        *(float4*)(g_qr + (size_t)bh*ND_ + d) = o;
    } else {
        int row  = (blockIdx.x - 1024) * 8 + (t >> 5);
        int lane = t & 31;
        float4 v = *(const float4*)(q_idx + (size_t)row*ID_ + lane*4);
        float m = fmaxf(fmaxf(fabsf(v.x), fabsf(v.y)), fmaxf(fabsf(v.z), fabsf(v.w)));
        #pragma unroll
        for (int o = 16; o; o >>= 1) m = fmaxf(m, __shfl_xor_sync(0xffffffffu, m, o));
        float scale = fmaxf(m, 1e-12f) * (1.f/127.f);
        if (scale < 1e-6f) scale = 1.f;
        int q0 = quant1(v.x, scale), q1 = quant1(v.y, scale);
        int q2 = quant1(v.z, scale), q3 = quant1(v.w, scale);
        unsigned w = (q0 & 0xFF) | ((q1 & 0xFF) << 8) | ((q2 & 0xFF) << 16) | ((q3 & 0xFF) << 24);
        g_qq[row*32 + lane] = w;
        if (lane == 0) g_qs[row] = scale;
    }
}

// ---------------- kernel 2: indexer, key-per-thread ----------------
__global__ void __launch_bounds__(256)
indexer_kernel(const float* __restrict__ k_idx_cache,
               const int* __restrict__ btbl,
               const int* __restrict__ seq_lens) {
    __shared__ int4  sqq[IH_][8];    // 64 heads x 32 words (as int4)
    __shared__ float sqs[IH_];
    int b = blockIdx.y, chunk = blockIdx.x;
    int t = threadIdx.x;

    const int4* src = (const int4*)(g_qq + b*IH_*32);
    for (int i = t; i < IH_*8; i += 256) ((int4*)sqq)[i] = src[i];
    if (t < IH_) sqs[t] = g_qs[b*IH_ + t];
    __syncthreads();

    int seqlen = seq_lens[b];
    int s = chunk*256 + t;
    int cs = min(s, seqlen-1);
    int pg = btbl[(b << 6) + (cs >> 6)];
    const float4* kr = (const float4*)(k_idx_cache + ((size_t)pg*BS_ + (cs & 63)) * ID_);

    // pass 1: row abs-max
    float mx = 0.f;
    #pragma unroll
    for (int i = 0; i < 32; i++) {
        float4 v = kr[i];
        mx = fmaxf(mx, fmaxf(fmaxf(fabsf(v.x), fabsf(v.y)), fmaxf(fabsf(v.z), fabsf(v.w))));
    }
    float scale = fmaxf(mx, 1e-12f) * (1.f/127.f);
    if (scale < 1e-6f) scale = 1.f;

    // pass 2: quantize + pack
    int kw[32];
    #pragma unroll
    for (int i = 0; i < 32; i++) {
        float4 v = kr[i];
        int q0 = quant1(v.x, scale), q1 = quant1(v.y, scale);
        int q2 = quant1(v.z, scale), q3 = quant1(v.w, scale);
        kw[i] = (q0 & 0xFF) | ((q1 & 0xFF) << 8) | ((q2 & 0xFF) << 16) | ((q3 & 0xFF) << 24);
    }

    // dp4a over 64 heads, 2-head ILP
    float tot = 0.f;
    #pragma unroll 4
    for (int h = 0; h < IH_; h += 2) {
        int a0 = 0, a1 = 0;
        #pragma unroll
        for (int wb = 0; wb < 8; wb++) {
            int4 x = sqq[h][wb];
            int4 y = sqq[h+1][wb];
            a0 = __dp4a(kw[wb*4+0], x.x, a0);
            a0 = __dp4a(kw[wb*4+1], x.y, a0);
            a0 = __dp4a(kw[wb*4+2], x.z, a0);
            a0 = __dp4a(kw[wb*4+3], x.w, a0);
            a1 = __dp4a(kw[wb*4+0], y.x, a1);
            a1 = __dp4a(kw[wb*4+1], y.y, a1);
            a1 = __dp4a(kw[wb*4+2], y.z, a1);
            a1 = __dp4a(kw[wb*4+3], y.w, a1);
        }
        tot = fmaf((float)a0, sqs[h],   tot);
        tot = fmaf((float)a1, sqs[h+1], tot);
    }
    g_iscore[b*SMAX_ + s] = (s < seqlen) ? tot * scale : __int_as_float(0xff800000);
}

// ---------------- kernel 3: exact top-k, 512 threads ----------------
__device__ __forceinline__ int exscan512(int v, int* sh, int* total) {
    int t = threadIdx.x, lane = t & 31, wid = t >> 5;
    __syncthreads();
    int incl = v;
    #pragma unroll
    for (int o = 1; o < 32; o <<= 1) {
        int n = __shfl_up_sync(0xffffffffu, incl, o);
        if (lane >= o) incl += n;
    }
    if (lane == 31) sh[wid] = incl;
    __syncthreads();
    if (wid == 0) {
        int x = (lane < 16) ? sh[lane] : 0;
        #pragma unroll
        for (int o = 1; o < 16; o <<= 1) {
            int n = __shfl_up_sync(0xffffffffu, x, o);
            if (lane >= o) x += n;
        }
        if (lane < 16) sh[lane] = x;
    }
    __syncthreads();
    int base = wid ? sh[wid-1] : 0;
    *total = sh[15];
    return base + incl - v;
}

__global__ void topk_kernel() {
    int b = blockIdx.x;
    __shared__ unsigned skey[SMAX_];
    __shared__ int hist[256];
    __shared__ int sscan[17];
    __shared__ int sinfo[2];
    __shared__ int stot;
    int t = threadIdx.x;
    int lane = t & 31, wid = t >> 5;

    for (int i = t; i < SMAX_; i += 512) {
        unsigned u = __float_as_uint(g_iscore[b*SMAX_ + i]);
        skey[i] = (u & 0x80000000u) ? ~u : (u | 0x80000000u);
    }
    __syncthreads();

    unsigned prefix = 0, mask = 0;
    int Krem = TOPK_;
    for (int shift = 24; shift >= 0; shift -= 8) {
        if (t < 256) hist[t] = 0;
        __syncthreads();
        for (int i = t; i < SMAX_; i += 512) {
            unsigned u = skey[i];
            if ((u & mask) == prefix) atomicAdd((unsigned*)&hist[(u >> shift) & 255], 1u);
        }
        __syncthreads();
        int c = (t < 256) ? hist[t] : 0;
        int incl = c;
        #pragma unroll
        for (int o = 1; o < 32; o <<= 1) {
            int n = __shfl_up_sync(0xffffffffu, incl, o);
            if (lane >= o) incl += n;
        }
        if (lane == 31 && wid < 8) sscan[wid] = incl;
        __syncthreads();
        if (wid == 0) {
            int x = (lane < 8) ? sscan[lane] : 0;
            #pragma unroll
            for (int o = 1; o < 8; o <<= 1) {
                int n = __shfl_up_sync(0xffffffffu, x, o);
                if (lane >= o) x += n;
            }
            if (lane < 8) sscan[lane] = x;
            if (lane == 7) stot = x;
        }
        __syncthreads();
        if (t < 256) {
            int P = incl + (wid ? sscan[wid-1] : 0);
            int above = stot - P;
            if (above < Krem && Krem <= above + c) {
                sinfo[0] = t;
                sinfo[1] = Krem - above;
            }
        }
        __syncthreads();
        prefix |= ((unsigned)sinfo[0]) << shift;
        mask   |= 0xFFu << shift;
        Krem = sinfo[1];
        __syncthreads();
    }
    unsigned T = prefix;
    int R = Krem;

    int base = t * 8;
    int eqc = 0;
    #pragma unroll
    for (int i = 0; i < 8; i++) eqc += (skey[base+i] == T);
    int tot;
    int eqoff = exscan512(eqc, sscan, &tot);

    int kc = 0;
    unsigned kmask = 0;
    int er = eqoff;
    #pragma unroll
    for (int i = 0; i < 8; i++) {
        unsigned u = skey[base+i];
        bool eq = (u == T);
        bool kp = (u > T) || (eq && er < R);
        er += eq;
        if (base + i == 0) g_has0[b] = kp ? 1 : 0;   // only thread 0
        kmask |= (unsigned)kp << i;
        kc += kp;
    }
    int koff = exscan512(kc, sscan, &tot);
    int p = koff;
    #pragma unroll
    for (int i = 0; i < 8; i++) {
        if ((kmask >> i) & 1) g_sel[b*TOPK_ + p++] = base + i;
    }
}

// ---------------- kernel 4: split-KV attention (256 keys per CTA) ----------------
struct AttnSmem {
    float q[16][ND_];       // 32768
    float k[2][64][128];    // 65536 swizzled
    float sc[16][256];      // 16384
};                          // 114688 B

extern __shared__ char smem_raw[];

__device__ __forceinline__ void prefetch_tile(AttnSmem& S, int buf, int tile, int ch,
                                              int selbase,
                                              const float* __restrict__ kv,
                                              const int* __restrict__ btbl,
                                              int bq, int t) {
    int kbase = tile << 6;
    int g = t & 31;
    int dstg = g ^ ((t >> 5) & 7);
    #pragma unroll
    for (int i = 0; i < 8; i++) {
        int r = (t >> 5) + (i << 3);
        int sp = g_sel[selbase + kbase + r];
        int pg = btbl[bq + (sp >> 6)];
        const float* src = kv + ((size_t)pg*BS_ + (sp & 63)) * ND_ + (ch << 7) + (g << 2);
        cpa16(&S.k[buf][r][dstg << 2], src);
    }
    CP_COMMIT();
}

__global__ void __launch_bounds__(256, 2)
attn_kernel(const float* __restrict__ kv,
            const float* __restrict__ attn_sink,
            const int* __restrict__ btbl) {
    AttnSmem& S = *(AttnSmem*)smem_raw;
    int hg = blockIdx.x, b = blockIdx.y, split = blockIdx.z;
    int t = threadIdx.x;
    int hbase = hg * 16;
    int selbase = b*TOPK_ + split*256;
    int bq = b << 6;
    int slot = (b*4 + hg)*2 + split;

    // load q + zero scores
    {
        const float* qr = g_qr + ((size_t)b*NH_ + hbase) * ND_;
        for (int i = t*4; i < 16*ND_; i += 1024)
            *(float4*)&S.q[0][i] = *(const float4*)(qr + i);
        for (int i = t; i < 16*256; i += 256) (&S.sc[0][0])[i] = 0.f;
    }
    prefetch_tile(S, 0, 0, 0, selbase, kv, btbl, bq, t);
    __syncthreads();

    int w  = t >> 5;
    int kx = t & 31;
    int x7 = kx & 7;
    int hg4 = (w >> 1) << 2;      // phase A: head quad
    int dgb = (w & 1) << 4;       // phase A: granule base (d-half)

    // ======== phase A: scores ========
    ull accA[4][2];
    int buf = 0;
    #pragma unroll 1
    for (int s = 0; s < 16; s++) {
        CP_WAIT0();
        __syncthreads();
        if (s < 15) prefetch_tile(S, buf^1, (s+1) >> 2, (s+1) & 3, selbase, kv, btbl, bq, t);
        else        prefetch_tile(S, buf^1, 0, 0, selbase, kv, btbl, bq, t);  // first C stage
        int tile = s >> 2, ch = s & 3;
        if (ch == 0) {
            #pragma unroll
            for (int h = 0; h < 4; h++) { accA[h][0] = 0ull; accA[h][1] = 0ull; }
        }
        const float* kb0 = &S.k[buf][kx][0];
        const float* kb1 = &S.k[buf][kx+32][0];
        #pragma unroll
        for (int gg = 0; gg < 16; gg++) {
            int g = dgb + gg;
            int off = (g ^ x7) << 2;
            ulonglong2 ka = *(const ulonglong2*)(kb0 + off);
            ulonglong2 kc = *(const ulonglong2*)(kb1 + off);
            int d = (ch << 7) + (g << 2);
            #pragma unroll
            for (int h = 0; h < 4; h++) {
                ulonglong2 qa = *(const ulonglong2*)&S.q[hg4+h][d];
                FMA2(accA[h][0], qa.x, ka.x, accA[h][0]);
                FMA2(accA[h][0], qa.y, ka.y, accA[h][0]);
                FMA2(accA[h][1], qa.x, kc.x, accA[h][1]);
                FMA2(accA[h][1], qa.y, kc.y, accA[h][1]);
            }
        }
        if (ch == 3) {
            int j0 = (tile << 6) + kx, j1 = j0 + 32;
            #pragma unroll
            for (int h = 0; h < 4; h++) {
                float2 u0 = unpack2(accA[h][0]);
                float2 u1 = unpack2(accA[h][1]);
                atomicAdd(&S.sc[hg4+h][j0], (u0.x + u0.y) * SCALE_);
                atomicAdd(&S.sc[hg4+h][j1], (u1.x + u1.y) * SCALE_);
            }
        }
        buf ^= 1;
    }
    __syncthreads();

    // sink add (deterministic, single thread per head)
    if (split == 0 && t < 16) {
        if (g_sel[selbase] == 0) S.sc[t][0] += attn_sink[hbase + t];
    }
    __syncthreads();

    // ======== softmax partials (warp per 2 heads) ========
    {
        int jt = t & 31;
        #pragma unroll
        for (int hh = 0; hh < 2; hh++) {
            int hloc = 2*w + hh;
            float m = -3.4e38f;
            #pragma unroll
            for (int j = jt; j < 256; j += 32) m = fmaxf(m, S.sc[hloc][j]);
            #pragma unroll
            for (int o = 16; o; o >>= 1) m = fmaxf(m, __shfl_xor_sync(0xffffffffu, m, o));
            float sum = 0.f;
            #pragma unroll
            for (int j = jt; j < 256; j += 32) {
                float e = expf(S.sc[hloc][j] - m);
                S.sc[hloc][j] = e;
                sum += e;
            }
            #pragma unroll
            for (int o = 16; o; o >>= 1) sum += __shfl_xor_sync(0xffffffffu, sum, o);
            if (jt == 0) g_pml[slot*16 + hloc] = make_float2(m, sum);
        }
    }

    // ======== phase C: unnormalized output ========
    int hq = (t >> 6) << 2;   // 4 heads, 64 d-lanes
    int pd = t & 63;
    int gC = pd >> 1;
    int o2 = (pd & 1) << 1;
    #pragma unroll 1
    for (int ch = 0; ch < 4; ch++) {
        ull a0 = 0ull, a1 = 0ull, a2 = 0ull, a3 = 0ull;
        #pragma unroll 1
        for (int tile = 0; tile < 4; tile++) {
            CP_WAIT0();
            __syncthreads();
            int s = ch*4 + tile;
            if (s < 15) {
                int ns = s + 1;
                prefetch_tile(S, buf^1, ns & 3, ns >> 2, selbase, kv, btbl, bq, t);
            }
            int kbase = tile << 6;
            const float* pw0 = &S.sc[hq+0][kbase];
            const float* pw1 = &S.sc[hq+1][kbase];
            const float* pw2 = &S.sc[hq+2][kbase];
            const float* pw3 = &S.sc[hq+3][kbase];
            const float* kbB = &S.k[buf][0][0];
            #pragma unroll 4
            for (int j = 0; j < 64; j += 4) {
                float4 w0 = *(const float4*)(pw0 + j);
                float4 w1 = *(const float4*)(pw1 + j);
                float4 w2 = *(const float4*)(pw2 + j);
                float4 w3 = *(const float4*)(pw3 + j);
                #pragma unroll
                for (int jj = 0; jj < 4; jj++) {
                    int row = j + jj;
                    ull kp = *(const ull*)(kbB + (row << 7) + ((gC ^ (row & 7)) << 2) + o2);
                    FMA2(a0, dup2((&w0.x)[jj]), kp, a0);
                    FMA2(a1, dup2((&w1.x)[jj]), kp, a1);
                    FMA2(a2, dup2((&w2.x)[jj]), kp, a2);
                    FMA2(a3, dup2((&w3.x)[jj]), kp, a3);
                }
            }
            buf ^= 1;
        }
        int dloc = (ch << 7) + (pd << 1);
        float* po = g_pO + ((size_t)slot*16)*ND_;
        float2 u;
        u = unpack2(a0); *(float2*)(po + (size_t)(hq+0)*ND_ + dloc) = u;
        u = unpack2(a1); *(float2*)(po + (size_t)(hq+1)*ND_ + dloc) = u;
        u = unpack2(a2); *(float2*)(po + (size_t)(hq+2)*ND_ + dloc) = u;
        u = unpack2(a3); *(float2*)(po + (size_t)(hq+3)*ND_ + dloc) = u;
    }
}

// ---------------- kernel 5: flash combine + optional key-0 term ----------------
__global__ void combine_kernel(const float* __restrict__ kv,
                               const float* __restrict__ attn_sink,
                               const int* __restrict__ btbl,
                               float* __restrict__ out) {
    __shared__ float k0s[512];
    __shared__ float s0sh[16];
    int hg = blockIdx.x, b = blockIdx.y;
    int t = threadIdx.x;
    int hbase = hg * 16;

    const float* k0 = kv + (size_t)btbl[b << 6] * (BS_ * ND_);  // s=0 row
    {
        int i = t * 2;
        *(float2*)(k0s + i) = *(const float2*)(k0 + i);
    }
    __syncthreads();

    int h = t >> 4, ln = t & 15;
    // score of key 0 for this head
    {
        const float* qr = g_qr + ((size_t)b*NH_ + hbase + h)*ND_ + ln*32;
        const float* kk = k0s + ln*32;
        float acc = 0.f;
        #pragma unroll
        for (int i = 0; i < 32; i++) acc = fmaf(qr[i], kk[i], acc);
        #pragma unroll
        for (int o = 8; o; o >>= 1) acc += __shfl_xor_sync(0xffffffffu, acc, o);
        if (ln == 0) s0sh[h] = acc * SCALE_ + attn_sink[hbase + h];
    }
    __syncthreads();

    int dbase = ln * 32;
    int slot0 = (b*4 + hg)*2;
    float2 ml0 = g_pml[slot0*16 + h];
    float2 ml1 = g_pml[(slot0+1)*16 + h];
    int has0 = g_has0[b];
    float sc0 = s0sh[h];
    float M = fmaxf(ml0.x, ml1.x);
    if (!has0) M = fmaxf(M, sc0);
    float a0 = expf(ml0.x - M), a1 = expf(ml1.x - M);
    float a2 = has0 ? 0.f : expf(sc0 - M);
    float inv = 1.f / (ml0.y * a0 + ml1.y * a1 + a2);
    float c0 = a0 * inv, c1 = a1 * inv, c2 = a2 * inv;

    const float* p0 = g_pO + ((size_t)slot0*16 + h)*ND_ + dbase;
    const float* p1 = g_pO + ((size_t)(slot0+1)*16 + h)*ND_ + dbase;
    float* po = out + ((size_t)b*NH_ + hbase + h)*ND_ + dbase;
    #pragma unroll
    for (int i = 0; i < 8; i++) {
        float4 v0 = *(const float4*)(p0 + i*4);
        float4 v1 = *(const float4*)(p1 + i*4);
        float4 vk = *(const float4*)(k0s + dbase + i*4);
        float4 o;
        o.x = v0.x*c0 + v1.x*c1 + vk.x*c2;
        o.y = v0.y*c0 + v1.y*c1 + vk.y*c2;
        o.z = v0.z*c0 + v1.z*c1 + vk.z*c2;
        o.w = v0.w*c0 + v1.w*c1 + vk.w*c2;
        *(float4*)(po + i*4) = o;
    }
}

// ---------------- launch ----------------
extern "C" void kernel_launch(void* const* d_in, const int* in_sizes, int n_in,
                              void* d_out, int out_size) {
    const float* q      = (const float*)d_in[0];
    const float* cosp   = (const float*)d_in[1];
    const float* sinp   = (const float*)d_in[2];
    const float* kv     = (const float*)d_in[3];
    const float* q_idx  = (const float*)d_in[4];
    const float* k_idx  = (const float*)d_in[5];
    const float* sink   = (const float*)d_in[6];
    const int*   btbl   = (const int*)d_in[7];
    const int*   slens  = (const int*)d_in[8];
    float* out = (float*)d_out;

    prep_kernel<<<1280, 256>>>(q, cosp, sinp, q_idx);
    indexer_kernel<<<dim3(16, NB_), 256>>>(k_idx, btbl, slens);
    topk_kernel<<<NB_, 512>>>();

    int smem = (int)sizeof(AttnSmem);
    cudaFuncSetAttribute(attn_kernel, cudaFuncAttributeMaxDynamicSharedMemorySize, smem);
    attn_kernel<<<dim3(4, NB_, 2), 256, smem>>>(kv, sink, btbl);
    combine_kernel<<<dim3(4, NB_), 256>>>(kv, sink, btbl, out);
}